// round 9
// baseline (speedup 1.0000x reference)
#include <cuda_runtime.h>
#include <cuda_bf16.h>
#include <cstdint>

#define T 1024
#define BATCH 64
#define NGEMM 48            // 3 branches * 16 tile-pairs

// ---------------- device scratch (no allocations allowed) ----------------
__device__ unsigned short d_ghi[3][BATCH][T];   // bf16 hi split of sigmoid rows
__device__ unsigned short d_glo[3][BATCH][T];   // bf16 lo split
__device__ float d_Spart[3][16][BATCH];         // per-branch, per-pair partial S
__device__ int   d_ctr;                         // finisher counter (reset each run)

__device__ __forceinline__ float clamp01(float v) { return fminf(fmaxf(v, 0.f), 1.f); }
__device__ __forceinline__ unsigned short f2bf(float f) {
    return __bfloat16_as_ushort(__float2bfloat16(f));
}
__device__ __forceinline__ float bf2f(unsigned short u) {
    return __bfloat162float(__ushort_as_bfloat16(u));
}

// m16n8k16 bf16 HMMA, fp32 accum in place (baseline ISA, works on sm_103)
__device__ __forceinline__ void hmma(float* d, uint32_t a0, uint32_t a1,
                                     uint32_t a2, uint32_t a3,
                                     uint32_t b0, uint32_t b1) {
    asm volatile(
        "mma.sync.aligned.m16n8k16.row.col.f32.bf16.bf16.f32 "
        "{%0,%1,%2,%3}, {%4,%5,%6,%7}, {%8,%9}, {%0,%1,%2,%3};"
        : "+f"(d[0]), "+f"(d[1]), "+f"(d[2]), "+f"(d[3])
        : "r"(a0), "r"(a1), "r"(a2), "r"(a3), "r"(b0), "r"(b1));
}

// ---------------- block reductions (256 threads, 8 warps) ----------------
__shared__ float sRA[8], sRB[8], sWsum[8], sWexcl[8];

__device__ __forceinline__ void blockMax2(float& a, float& b) {
    int w = threadIdx.x >> 5, l = threadIdx.x & 31;
    #pragma unroll
    for (int off = 16; off; off >>= 1) {
        a = fmaxf(a, __shfl_xor_sync(0xffffffffu, a, off));
        b = fmaxf(b, __shfl_xor_sync(0xffffffffu, b, off));
    }
    if (l == 0) { sRA[w] = a; sRB[w] = b; }
    __syncthreads();
    if (threadIdx.x == 0) {
        float ma = sRA[0], mb = sRB[0];
        #pragma unroll
        for (int k = 1; k < 8; k++) { ma = fmaxf(ma, sRA[k]); mb = fmaxf(mb, sRB[k]); }
        sRA[0] = ma; sRB[0] = mb;
    }
    __syncthreads();
    a = sRA[0]; b = sRB[0];
    __syncthreads();
}
__device__ __forceinline__ void blockSum2(float& a, float& b) {
    int w = threadIdx.x >> 5, l = threadIdx.x & 31;
    #pragma unroll
    for (int off = 16; off; off >>= 1) {
        a += __shfl_xor_sync(0xffffffffu, a, off);
        b += __shfl_xor_sync(0xffffffffu, b, off);
    }
    if (l == 0) { sRA[w] = a; sRB[w] = b; }
    __syncthreads();
    if (threadIdx.x == 0) {
        float sa = sRA[0], sb = sRB[0];
        #pragma unroll
        for (int k = 1; k < 8; k++) { sa += sRA[k]; sb += sRB[k]; }
        sRA[0] = sa; sRB[0] = sb;
    }
    __syncthreads();
    a = sRA[0]; b = sRB[0];
    __syncthreads();
}

// ---------------------------------------------------------------------------
// Setup kernel: sigmoid rows -> bf16 hi/lo splits in gmem. 192 blocks x 128.
// ---------------------------------------------------------------------------
__global__ void __launch_bounds__(128) setup_kernel(
    const float* __restrict__ x1, const float* __restrict__ x2, const float* __restrict__ x3,
    const float* __restrict__ t1p, const float* __restrict__ b1p,
    const float* __restrict__ t2p, const float* __restrict__ b2p,
    const float* __restrict__ t3p, const float* __restrict__ b3p)
{
    int bid = blockIdx.x;
    int br = bid >> 6;
    int b = bid & 63;
    const float* xs = (br == 0) ? x1 : (br == 1) ? x2 : x3;
    const float* tp = (br == 0) ? t1p : (br == 1) ? t2p : t3p;
    const float* bp = (br == 0) ? b1p : (br == 1) ? b2p : b3p;
    float tv = tp[0], bv = bp[0];
    int t = threadIdx.x;

    const float* xr = xs + b * T;
    float xv[8];
    *(float4*)(xv + 0) = *(const float4*)(xr + 8 * t);
    *(float4*)(xv + 4) = *(const float4*)(xr + 8 * t + 4);

    uint32_t hiw[4], low[4];
    #pragma unroll
    for (int q = 0; q < 4; q++) {
        unsigned short h2[2], l2[2];
        #pragma unroll
        for (int e = 0; e < 2; e++) {
            float prod = __fmul_rn(xv[2 * q + e], tv);   // no contraction: exact r==b test
            float r = __fsub_rn(bv, prod);
            if (r == bv) r = -10.f;
            float g = __fdividef(1.f, 1.f + __expf(-r));
            h2[e] = f2bf(g);
            l2[e] = f2bf(g - bf2f(h2[e]));
        }
        hiw[q] = (uint32_t)h2[0] | ((uint32_t)h2[1] << 16);
        low[q] = (uint32_t)l2[0] | ((uint32_t)l2[1] << 16);
    }
    *(uint4*)(&d_ghi[br][b][8 * t]) = make_uint4(hiw[0], hiw[1], hiw[2], hiw[3]);
    *(uint4*)(&d_glo[br][b][8 * t]) = make_uint4(low[0], low[1], low[2], low[3]);
}

// ---------------------------------------------------------------------------
// GEMM kernel: 48 CTAs x 256 threads. CTA = (br, pair t). Two 32-row i-tiles
// (I0 = 32t and 32(31-t)); warp w owns b-columns 8w..8w+7 and sweeps the full
// K range once; B fragments shared between both tiles in the overlap region.
// A fragments come straight from zero-padded bf16 a1sm arrays (Toeplitz
// structure: a3 == a0, 5 distinct u32 per split per tile per k-step).
// ---------------------------------------------------------------------------
#define AESZ 1112   // u16 entries per ext array (idx = 32 + (k - i), zeros outside)

__global__ void __launch_bounds__(256) gemm_kernel(
    const float* __restrict__ A1a, const float* __restrict__ A1b, const float* __restrict__ A1c,
    const float* __restrict__ A2a, const float* __restrict__ A2b, const float* __restrict__ A2c,
    const float* __restrict__ ba1, const float* __restrict__ ba2, const float* __restrict__ ba3,
    const float* __restrict__ bb1, const float* __restrict__ bb2, const float* __restrict__ bb3,
    const float* __restrict__ A4, const float* __restrict__ beta4p,
    float* __restrict__ out)
{
    __shared__ __align__(16) unsigned short aeh0[AESZ], aeh1[AESZ];
    __shared__ __align__(16) unsigned short ael0[AESZ], ael1[AESZ];
    __shared__ __align__(16) float sAf[1024];
    __shared__ __align__(16) float sSuf[1024];
    __shared__ __align__(16) float sA2f[1024];
    __shared__ __align__(16) float sD[2][32][66];
    __shared__ float sBlk[256];
    __shared__ int sDone;

    const float SIG10 = 4.5397868702434395e-05f;

    int bid = blockIdx.x;
    int br = bid / 16;
    int tp = bid % 16;                 // pair index
    int I0A = 32 * tp;
    int I0B = 32 * (31 - tp);
    int nk  = 64 - 2 * tp;             // k-steps (16 wide) from I0A to 1024
    int ksB = 2 * (31 - 2 * tp);       // first k-step that overlaps tile B

    const float* A1  = (br == 0) ? A1a : (br == 1) ? A1b : A1c;
    const float* A2  = (br == 0) ? A2a : (br == 1) ? A2b : A2c;
    const float* bap = (br == 0) ? ba1 : (br == 1) ? ba2 : ba3;

    int t = threadIdx.x;
    int w = t >> 5, l = t & 31;
    int roff = l >> 2;                 // fragment row offset 0..7
    int cq = l & 3;                    // fragment k-pair 0..3

    // ---- preamble: fp32 softmax(A1)+suffix scan, softmax(A2) ----
    float ba = bap[0];
    {
        float4 v1 = *(const float4*)(A1 + 4 * t);
        float4 v2 = *(const float4*)(A2 + 4 * t);
        float m1 = fmaxf(fmaxf(v1.x, v1.y), fmaxf(v1.z, v1.w));
        float m2 = fmaxf(fmaxf(v2.x, v2.y), fmaxf(v2.z, v2.w));
        blockMax2(m1, m2);
        float e10 = __expf(v1.x - m1), e11 = __expf(v1.y - m1);
        float e12 = __expf(v1.z - m1), e13 = __expf(v1.w - m1);
        float e20 = __expf(v2.x - m2), e21 = __expf(v2.y - m2);
        float e22 = __expf(v2.z - m2), e23 = __expf(v2.w - m2);
        float s1 = (e10 + e11) + (e12 + e13);
        float s2 = (e20 + e21) + (e22 + e23);
        blockSum2(s1, s2);
        float inv1 = __fdividef(1.f, s1), inv2 = __fdividef(1.f, s2);
        float a0 = e10 * inv1, a1v = e11 * inv1, a2v = e12 * inv1, a3v = e13 * inv1;
        *(float4*)(sAf + 4 * t) = make_float4(a0, a1v, a2v, a3v);
        *(float4*)(sA2f + 4 * t) = make_float4(e20 * inv2, e21 * inv2, e22 * inv2, e23 * inv2);

        float sn = ((a0 + a1v) + (a2v + a3v));
        float s = sn;
        #pragma unroll
        for (int off = 1; off < 32; off <<= 1) {
            float o = __shfl_down_sync(0xffffffffu, s, off);
            if (l + off < 32) s += o;
        }
        if (l == 0) sWsum[w] = s;
        __syncthreads();
        if (t < 8) {
            float tot = 0.f;
            for (int k = t + 1; k < 8; k++) tot += sWsum[k];
            sWexcl[t] = tot;
        }
        __syncthreads();
        float after = (s - sn) + sWexcl[w];
        float v3s = after + a3v;
        float v2s = v3s + a2v;
        float v1s = v2s + a1v;
        float v0s = v1s + a0;
        sSuf[4 * t + 3] = v3s;
        sSuf[4 * t + 2] = v2s;
        sSuf[4 * t + 1] = v1s;
        sSuf[4 * t + 0] = v0s;
    }
    __syncthreads();

    // ---- build zero-padded bf16 split arrays (+1-shifted copies) ----
    for (int x = t; x < AESZ; x += 256) {
        float v0 = (x >= 32 && x < 1056) ? sAf[x - 32] : 0.f;
        float v1 = (x + 1 >= 32 && x + 1 < 1056) ? sAf[x - 31] : 0.f;
        unsigned short h0 = f2bf(v0);
        unsigned short h1 = f2bf(v1);
        aeh0[x] = h0; ael0[x] = f2bf(v0 - bf2f(h0));
        aeh1[x] = h1; ael1[x] = f2bf(v1 - bf2f(h1));
    }
    __syncthreads();

    // ---- main K loop ----
    const uint32_t* Ah = (const uint32_t*)((roff & 1) ? aeh1 : aeh0);
    const uint32_t* Al = (const uint32_t*)((roff & 1) ? ael1 : ael0);
    int Pc = 32 + 2 * cq - roff;       // thread-constant base (u16 units)

    int n = 8 * w + roff;              // batch column this thread serves
    const uint32_t* ghin = (const uint32_t*)&d_ghi[br][n][0];
    const uint32_t* glon = (const uint32_t*)&d_glo[br][n][0];

    float accA0[4] = {0, 0, 0, 0}, accA1[4] = {0, 0, 0, 0};
    float accB0[4] = {0, 0, 0, 0}, accB1[4] = {0, 0, 0, 0};

    uint32_t bq[2][4];
    {
        int kw0 = ((I0A) >> 1) + cq;
        bq[0][0] = __ldg(ghin + kw0); bq[0][1] = __ldg(ghin + kw0 + 4);
        bq[0][2] = __ldg(glon + kw0); bq[0][3] = __ldg(glon + kw0 + 4);
        int kw1 = kw0 + 8;
        bq[1][0] = __ldg(ghin + kw1); bq[1][1] = __ldg(ghin + kw1 + 4);
        bq[1][2] = __ldg(glon + kw1); bq[1][3] = __ldg(glon + kw1 + 4);
    }

    for (int ks = 0; ks < nk; ks++) {
        uint32_t bh0 = bq[ks & 1][0], bh1 = bq[ks & 1][1];
        uint32_t bl0 = bq[ks & 1][2], bl1 = bq[ks & 1][3];
        if (ks + 2 < nk) {
            int kw = ((I0A + 16 * (ks + 2)) >> 1) + cq;
            bq[ks & 1][0] = __ldg(ghin + kw); bq[ks & 1][1] = __ldg(ghin + kw + 4);
            bq[ks & 1][2] = __ldg(glon + kw); bq[ks & 1][3] = __ldg(glon + kw + 4);
        }

        // tile A
        {
            int Q0 = (Pc + 16 * ks) >> 1;
            uint32_t uh0 = Ah[Q0 - 12], uh1 = Ah[Q0 - 8], uh2 = Ah[Q0 - 4];
            uint32_t uh3 = Ah[Q0],      uh4 = Ah[Q0 + 4];
            uint32_t ul0 = Al[Q0 - 12], ul1 = Al[Q0 - 8], ul2 = Al[Q0 - 4];
            uint32_t ul3 = Al[Q0],      ul4 = Al[Q0 + 4];
            // rows 0-15 frag: {a0=u3, a1=u2, a2=u4, a3=u3}; rows 16-31: {u1,u0,u2,u1}
            hmma(accA0, uh3, uh2, uh4, uh3, bh0, bh1);
            hmma(accA0, uh3, uh2, uh4, uh3, bl0, bl1);
            hmma(accA0, ul3, ul2, ul4, ul3, bh0, bh1);
            hmma(accA1, uh1, uh0, uh2, uh1, bh0, bh1);
            hmma(accA1, uh1, uh0, uh2, uh1, bl0, bl1);
            hmma(accA1, ul1, ul0, ul2, ul1, bh0, bh1);
        }
        // tile B (overlap region)
        if (ks >= ksB) {
            int Q0 = (Pc + 16 * (ks - ksB)) >> 1;
            uint32_t uh0 = Ah[Q0 - 12], uh1 = Ah[Q0 - 8], uh2 = Ah[Q0 - 4];
            uint32_t uh3 = Ah[Q0],      uh4 = Ah[Q0 + 4];
            uint32_t ul0 = Al[Q0 - 12], ul1 = Al[Q0 - 8], ul2 = Al[Q0 - 4];
            uint32_t ul3 = Al[Q0],      ul4 = Al[Q0 + 4];
            hmma(accB0, uh3, uh2, uh4, uh3, bh0, bh1);
            hmma(accB0, uh3, uh2, uh4, uh3, bl0, bl1);
            hmma(accB0, ul3, ul2, ul4, ul3, bh0, bh1);
            hmma(accB1, uh1, uh0, uh2, uh1, bh0, bh1);
            hmma(accB1, uh1, uh0, uh2, uh1, bl0, bl1);
            hmma(accB1, ul1, ul0, ul2, ul1, bh0, bh1);
        }
    }

    // ---- store D fragments to smem ----
    {
        int c0 = 8 * w + 2 * cq;
        sD[0][roff +  0][c0] = accA0[0]; sD[0][roff +  0][c0 + 1] = accA0[1];
        sD[0][roff +  8][c0] = accA0[2]; sD[0][roff +  8][c0 + 1] = accA0[3];
        sD[0][roff + 16][c0] = accA1[0]; sD[0][roff + 16][c0 + 1] = accA1[1];
        sD[0][roff + 24][c0] = accA1[2]; sD[0][roff + 24][c0 + 1] = accA1[3];
        sD[1][roff +  0][c0] = accB0[0]; sD[1][roff +  0][c0 + 1] = accB0[1];
        sD[1][roff +  8][c0] = accB0[2]; sD[1][roff +  8][c0 + 1] = accB0[3];
        sD[1][roff + 16][c0] = accB1[0]; sD[1][roff + 16][c0 + 1] = accB1[1];
        sD[1][roff + 24][c0] = accB1[2]; sD[1][roff + 24][c0 + 1] = accB1[3];
    }
    __syncthreads();

    // ---- epilogue: tail, clip, A2-weight, per-b reduce ----
    {
        int b = t & 63, grp = t >> 6;
        float local = 0.f;
        #pragma unroll
        for (int rr = 0; rr < 16; rr++) {
            int idx = grp * 16 + rr;      // 0..63
            int tile = idx >> 5;
            int row = idx & 31;
            int i = (tile ? I0B : I0A) + row;
            float ssuf = (i == 0) ? 0.f : sSuf[1024 - i];
            float wb1 = sD[tile][row][b] + (1.f - ba) + SIG10 * ssuf;
            local += sA2f[i] * (1.f - clamp01(wb1));
        }
        sBlk[t] = local;
    }
    __syncthreads();
    if (t < 64) {
        float S = sBlk[t] + sBlk[64 + t] + sBlk[128 + t] + sBlk[192 + t];
        d_Spart[br][tp][t] = S;
    }

    // ---- last-CTA final combine ----
    __threadfence();
    if (t == 0) {
        int v = atomicAdd(&d_ctr, 1);
        sDone = (v == NGEMM - 1) ? 1 : 0;
    }
    __syncthreads();
    if (sDone) {
        if (t < BATCH) {
            float e0 = __expf(A4[0]), e1 = __expf(A4[1]), e2 = __expf(A4[2]);
            float sinv = __fdividef(1.f, e0 + e1 + e2);
            float a40 = e0 * sinv, a41 = e1 * sinv, a42 = e2 * sinv;
            volatile float* vs = (volatile float*)d_Spart;   // [3][16][64]
            float Sb[3];
            #pragma unroll
            for (int r = 0; r < 3; r++) {
                float acc = 0.f;
                #pragma unroll
                for (int p = 0; p < 16; p++) acc += vs[(r * 16 + p) * 64 + t];
                Sb[r] = acc;
            }
            float r0 = clamp01(bb1[0] - Sb[0]);
            float r1 = clamp01(bb2[0] - Sb[1]);
            float r2 = clamp01(bb3[0] - Sb[2]);
            float acc4 = beta4p[0];
            acc4 -= a40 * (1.f - r0);
            acc4 -= a41 * (1.f - r1);
            acc4 -= a42 * (1.f - r2);
            out[t] = clamp01(acc4);
        }
        if (t == 0) d_ctr = 0;
    }
}

extern "C" void kernel_launch(void* const* d_in, const int* in_sizes, int n_in,
                              void* d_out, int out_size)
{
    const float* x1      = (const float*)d_in[0];
    const float* x2      = (const float*)d_in[1];
    const float* x3      = (const float*)d_in[2];
    const float* t1      = (const float*)d_in[3];
    const float* b1      = (const float*)d_in[4];
    const float* A1_1    = (const float*)d_in[5];
    const float* A2_1    = (const float*)d_in[6];
    const float* beta1_1 = (const float*)d_in[7];
    const float* beta1_2 = (const float*)d_in[8];
    const float* t2      = (const float*)d_in[9];
    const float* b2      = (const float*)d_in[10];
    const float* A1_2    = (const float*)d_in[11];
    const float* A2_2    = (const float*)d_in[12];
    const float* beta2_1 = (const float*)d_in[13];
    const float* beta2_2 = (const float*)d_in[14];
    const float* t3      = (const float*)d_in[15];
    const float* b3      = (const float*)d_in[16];
    const float* A1_3    = (const float*)d_in[17];
    const float* A2_3    = (const float*)d_in[18];
    const float* beta3_1 = (const float*)d_in[19];
    const float* beta3_2 = (const float*)d_in[20];
    const float* A4      = (const float*)d_in[21];
    const float* beta4   = (const float*)d_in[22];
    float* out = (float*)d_out;

    setup_kernel<<<192, 128>>>(x1, x2, x3, t1, b1, t2, b2, t3, b3);
    gemm_kernel<<<NGEMM, 256>>>(A1_1, A1_2, A1_3,
                                A2_1, A2_2, A2_3,
                                beta1_1, beta2_1, beta3_1,
                                beta1_2, beta2_2, beta3_2,
                                A4, beta4, out);
}

// round 10
// speedup vs baseline: 1.4133x; 1.4133x over previous
#include <cuda_runtime.h>
#include <cuda_bf16.h>
#include <cstdint>

#define T 1024
#define BATCH 64
#define NGEMM 96            // 3 branches * 16 tile-pairs * 2 b-halves

// ---------------- device scratch (no allocations allowed) ----------------
__device__ unsigned short d_ghi[3][BATCH][T];   // bf16 hi split of sigmoid rows
__device__ unsigned short d_glo[3][BATCH][T];   // bf16 lo split
__device__ float d_Spart[3][16][BATCH];         // per-branch, per-pair partial S
__device__ int   d_ctr;                         // finisher counter (reset each run)

__device__ __forceinline__ float clamp01(float v) { return fminf(fmaxf(v, 0.f), 1.f); }
__device__ __forceinline__ unsigned short f2bf(float f) {
    return __bfloat16_as_ushort(__float2bfloat16(f));
}
__device__ __forceinline__ float bf2f(unsigned short u) {
    return __bfloat162float(__ushort_as_bfloat16(u));
}

// m16n8k16 bf16 HMMA, fp32 accum in place (baseline ISA, works on sm_103)
__device__ __forceinline__ void hmma(float* d, uint32_t a0, uint32_t a1,
                                     uint32_t a2, uint32_t a3,
                                     uint32_t b0, uint32_t b1) {
    asm volatile(
        "mma.sync.aligned.m16n8k16.row.col.f32.bf16.bf16.f32 "
        "{%0,%1,%2,%3}, {%4,%5,%6,%7}, {%8,%9}, {%0,%1,%2,%3};"
        : "+f"(d[0]), "+f"(d[1]), "+f"(d[2]), "+f"(d[3])
        : "r"(a0), "r"(a1), "r"(a2), "r"(a3), "r"(b0), "r"(b1));
}

// ---------------------------------------------------------------------------
// Setup kernel: sigmoid rows -> bf16 hi/lo splits in gmem. 192 blocks x 128.
// ---------------------------------------------------------------------------
__global__ void __launch_bounds__(128) setup_kernel(
    const float* __restrict__ x1, const float* __restrict__ x2, const float* __restrict__ x3,
    const float* __restrict__ t1p, const float* __restrict__ b1p,
    const float* __restrict__ t2p, const float* __restrict__ b2p,
    const float* __restrict__ t3p, const float* __restrict__ b3p)
{
    int bid = blockIdx.x;
    int br = bid >> 6;
    int b = bid & 63;
    const float* xs = (br == 0) ? x1 : (br == 1) ? x2 : x3;
    const float* tp = (br == 0) ? t1p : (br == 1) ? t2p : t3p;
    const float* bp = (br == 0) ? b1p : (br == 1) ? b2p : b3p;
    float tv = tp[0], bv = bp[0];
    int t = threadIdx.x;

    const float* xr = xs + b * T;
    float xv[8];
    *(float4*)(xv + 0) = *(const float4*)(xr + 8 * t);
    *(float4*)(xv + 4) = *(const float4*)(xr + 8 * t + 4);

    uint32_t hiw[4], low[4];
    #pragma unroll
    for (int q = 0; q < 4; q++) {
        unsigned short h2[2], l2[2];
        #pragma unroll
        for (int e = 0; e < 2; e++) {
            float prod = __fmul_rn(xv[2 * q + e], tv);   // no contraction: exact r==b test
            float r = __fsub_rn(bv, prod);
            if (r == bv) r = -10.f;
            float g = __fdividef(1.f, 1.f + __expf(-r));
            h2[e] = f2bf(g);
            l2[e] = f2bf(g - bf2f(h2[e]));
        }
        hiw[q] = (uint32_t)h2[0] | ((uint32_t)h2[1] << 16);
        low[q] = (uint32_t)l2[0] | ((uint32_t)l2[1] << 16);
    }
    *(uint4*)(&d_ghi[br][b][8 * t]) = make_uint4(hiw[0], hiw[1], hiw[2], hiw[3]);
    *(uint4*)(&d_glo[br][b][8 * t]) = make_uint4(low[0], low[1], low[2], low[3]);
}

// ---------------------------------------------------------------------------
// GEMM kernel: 96 CTAs x 512 threads. CTA = (br, pair tp, bhalf).
// Two mirrored 32-row i-tiles; 16 warps = (4 col-groups of 8 b) x (4 k-parities).
// A fragments from zero-padded bf16 a1sm (Toeplitz; a3 == a0).
// ---------------------------------------------------------------------------
#define AESZ 1112   // u16 entries per ext array (idx = 32 + (k - i), zeros outside)

__global__ void __launch_bounds__(512) gemm_kernel(
    const float* __restrict__ A1a, const float* __restrict__ A1b, const float* __restrict__ A1c,
    const float* __restrict__ A2a, const float* __restrict__ A2b, const float* __restrict__ A2c,
    const float* __restrict__ ba1, const float* __restrict__ ba2, const float* __restrict__ ba3,
    const float* __restrict__ bb1, const float* __restrict__ bb2, const float* __restrict__ bb3,
    const float* __restrict__ A4, const float* __restrict__ beta4p,
    float* __restrict__ out)
{
    __shared__ __align__(16) unsigned short aeh0[AESZ], aeh1[AESZ];
    __shared__ __align__(16) unsigned short ael0[AESZ], ael1[AESZ];
    __shared__ __align__(16) float sAf[1024];
    __shared__ __align__(16) float sSuf[1024];
    __shared__ __align__(16) float sA2f[1024];
    __shared__ __align__(16) float sD[2][32][34];
    __shared__ float sBlk[512];
    __shared__ float sRA[16], sRB[16], sWsum[16], sWexcl[16];
    __shared__ int sDone;

    const float SIG10 = 4.5397868702434395e-05f;

    int bid = blockIdx.x;
    int br = bid >> 5;                 // 0..2
    int rem = bid & 31;
    int tp = rem >> 1;                 // pair 0..15
    int bhalf = rem & 1;
    int I0A = 32 * tp;
    int I0B = 32 * (31 - tp);
    int nk  = 64 - 2 * tp;             // k-steps from I0A to 1024
    int ksB = 2 * (31 - 2 * tp);       // first k-step overlapping tile B

    const float* A1  = (br == 0) ? A1a : (br == 1) ? A1b : A1c;
    const float* A2  = (br == 0) ? A2a : (br == 1) ? A2b : A2c;
    const float* bap = (br == 0) ? ba1 : (br == 1) ? ba2 : ba3;

    int t = threadIdx.x;
    int w = t >> 5, l = t & 31;
    int roff = l >> 2;                 // fragment row offset 0..7
    int cq = l & 3;                    // fragment k-pair 0..3
    int colg = w & 3;                  // col group (8 b each)
    int kpar = w >> 2;                 // k parity 0..3

    // ---- preamble: fp32 softmax(A1)+suffix scan, softmax(A2) (512 thr) ----
    float ba = bap[0];
    {
        float2 v1 = *(const float2*)(A1 + 2 * t);
        float2 v2 = *(const float2*)(A2 + 2 * t);
        float m1 = fmaxf(v1.x, v1.y);
        float m2 = fmaxf(v2.x, v2.y);
        // block max over 16 warps
        #pragma unroll
        for (int off = 16; off; off >>= 1) {
            m1 = fmaxf(m1, __shfl_xor_sync(0xffffffffu, m1, off));
            m2 = fmaxf(m2, __shfl_xor_sync(0xffffffffu, m2, off));
        }
        if (l == 0) { sRA[w] = m1; sRB[w] = m2; }
        __syncthreads();
        if (t == 0) {
            float a = sRA[0], b2 = sRB[0];
            #pragma unroll
            for (int k = 1; k < 16; k++) { a = fmaxf(a, sRA[k]); b2 = fmaxf(b2, sRB[k]); }
            sRA[0] = a; sRB[0] = b2;
        }
        __syncthreads();
        m1 = sRA[0]; m2 = sRB[0];
        __syncthreads();

        float e10 = __expf(v1.x - m1), e11 = __expf(v1.y - m1);
        float e20 = __expf(v2.x - m2), e21 = __expf(v2.y - m2);
        float s1 = e10 + e11, s2 = e20 + e21;
        #pragma unroll
        for (int off = 16; off; off >>= 1) {
            s1 += __shfl_xor_sync(0xffffffffu, s1, off);
            s2 += __shfl_xor_sync(0xffffffffu, s2, off);
        }
        if (l == 0) { sRA[w] = s1; sRB[w] = s2; }
        __syncthreads();
        if (t == 0) {
            float a = sRA[0], b2 = sRB[0];
            #pragma unroll
            for (int k = 1; k < 16; k++) { a += sRA[k]; b2 += sRB[k]; }
            sRA[0] = a; sRB[0] = b2;
        }
        __syncthreads();
        s1 = sRA[0]; s2 = sRB[0];
        __syncthreads();

        float inv1 = __fdividef(1.f, s1), inv2 = __fdividef(1.f, s2);
        float a0 = e10 * inv1, a1v = e11 * inv1;
        *(float2*)(sAf + 2 * t) = make_float2(a0, a1v);
        *(float2*)(sA2f + 2 * t) = make_float2(e20 * inv2, e21 * inv2);

        // inclusive suffix scan over 2-element thread chunks
        float sn = a0 + a1v;
        float s = sn;
        #pragma unroll
        for (int off = 1; off < 32; off <<= 1) {
            float o = __shfl_down_sync(0xffffffffu, s, off);
            if (l + off < 32) s += o;
        }
        if (l == 0) sWsum[w] = s;
        __syncthreads();
        if (t < 16) {
            float tot = 0.f;
            for (int k = t + 1; k < 16; k++) tot += sWsum[k];
            sWexcl[t] = tot;
        }
        __syncthreads();
        float after = (s - sn) + sWexcl[w];   // strictly-after my chunk
        float v1s = after + a1v;
        float v0s = v1s + a0;
        sSuf[2 * t + 1] = v1s;
        sSuf[2 * t + 0] = v0s;
    }
    __syncthreads();

    // ---- build zero-padded bf16 split arrays (+1-shifted copies) ----
    for (int x = t; x < AESZ; x += 512) {
        float v0 = (x >= 32 && x < 1056) ? sAf[x - 32] : 0.f;
        float v1 = (x + 1 >= 32 && x + 1 < 1056) ? sAf[x - 31] : 0.f;
        unsigned short h0 = f2bf(v0);
        unsigned short h1 = f2bf(v1);
        aeh0[x] = h0; ael0[x] = f2bf(v0 - bf2f(h0));
        aeh1[x] = h1; ael1[x] = f2bf(v1 - bf2f(h1));
    }
    __syncthreads();

    // ---- main K loop (warp handles ks = kpar, kpar+4, ...) ----
    const uint32_t* Ah = (const uint32_t*)((roff & 1) ? aeh1 : aeh0);
    const uint32_t* Al = (const uint32_t*)((roff & 1) ? ael1 : ael0);
    int Pc = 32 + 2 * cq - roff;       // thread-constant base (u16 units)

    int n = bhalf * 32 + 8 * colg + roff;
    const uint32_t* ghin = (const uint32_t*)&d_ghi[br][n][0];
    const uint32_t* glon = (const uint32_t*)&d_glo[br][n][0];

    float accA0[4] = {0, 0, 0, 0}, accA1[4] = {0, 0, 0, 0};
    float accB0[4] = {0, 0, 0, 0}, accB1[4] = {0, 0, 0, 0};

    uint32_t bq[2][4];
    {
        int k1 = (kpar + 4 < nk) ? (kpar + 4) : kpar;
        int kw0 = ((I0A + 16 * kpar) >> 1) + cq;
        int kw1 = ((I0A + 16 * k1) >> 1) + cq;
        bq[0][0] = __ldg(ghin + kw0); bq[0][1] = __ldg(ghin + kw0 + 4);
        bq[0][2] = __ldg(glon + kw0); bq[0][3] = __ldg(glon + kw0 + 4);
        bq[1][0] = __ldg(ghin + kw1); bq[1][1] = __ldg(ghin + kw1 + 4);
        bq[1][2] = __ldg(glon + kw1); bq[1][3] = __ldg(glon + kw1 + 4);
    }

    int it = 0;
    for (int ks = kpar; ks < nk; ks += 4, it++) {
        uint32_t bh0 = bq[it & 1][0], bh1 = bq[it & 1][1];
        uint32_t bl0 = bq[it & 1][2], bl1 = bq[it & 1][3];
        if (ks + 8 < nk) {
            int kw = ((I0A + 16 * (ks + 8)) >> 1) + cq;
            bq[it & 1][0] = __ldg(ghin + kw); bq[it & 1][1] = __ldg(ghin + kw + 4);
            bq[it & 1][2] = __ldg(glon + kw); bq[it & 1][3] = __ldg(glon + kw + 4);
        }

        // tile A
        {
            int Q0 = (Pc + 16 * ks) >> 1;
            uint32_t uh0 = Ah[Q0 - 12], uh1 = Ah[Q0 - 8], uh2 = Ah[Q0 - 4];
            uint32_t uh3 = Ah[Q0],      uh4 = Ah[Q0 + 4];
            uint32_t ul0 = Al[Q0 - 12], ul1 = Al[Q0 - 8], ul2 = Al[Q0 - 4];
            uint32_t ul3 = Al[Q0],      ul4 = Al[Q0 + 4];
            hmma(accA0, uh3, uh2, uh4, uh3, bh0, bh1);
            hmma(accA0, uh3, uh2, uh4, uh3, bl0, bl1);
            hmma(accA0, ul3, ul2, ul4, ul3, bh0, bh1);
            hmma(accA1, uh1, uh0, uh2, uh1, bh0, bh1);
            hmma(accA1, uh1, uh0, uh2, uh1, bl0, bl1);
            hmma(accA1, ul1, ul0, ul2, ul1, bh0, bh1);
        }
        // tile B (overlap region)
        if (ks >= ksB) {
            int Q0 = (Pc + 16 * (ks - ksB)) >> 1;
            uint32_t uh0 = Ah[Q0 - 12], uh1 = Ah[Q0 - 8], uh2 = Ah[Q0 - 4];
            uint32_t uh3 = Ah[Q0],      uh4 = Ah[Q0 + 4];
            uint32_t ul0 = Al[Q0 - 12], ul1 = Al[Q0 - 8], ul2 = Al[Q0 - 4];
            uint32_t ul3 = Al[Q0],      ul4 = Al[Q0 + 4];
            hmma(accB0, uh3, uh2, uh4, uh3, bh0, bh1);
            hmma(accB0, uh3, uh2, uh4, uh3, bl0, bl1);
            hmma(accB0, ul3, ul2, ul4, ul3, bh0, bh1);
            hmma(accB1, uh1, uh0, uh2, uh1, bh0, bh1);
            hmma(accB1, uh1, uh0, uh2, uh1, bl0, bl1);
            hmma(accB1, ul1, ul0, ul2, ul1, bh0, bh1);
        }
    }

    // ---- merge k-parity partials into sD (4 phased passes) ----
    {
        int c0 = 8 * colg + 2 * cq;
        #pragma unroll
        for (int p = 0; p < 4; p++) {
            if (kpar == p) {
                if (p == 0) {
                    sD[0][roff +  0][c0] = accA0[0]; sD[0][roff +  0][c0 + 1] = accA0[1];
                    sD[0][roff +  8][c0] = accA0[2]; sD[0][roff +  8][c0 + 1] = accA0[3];
                    sD[0][roff + 16][c0] = accA1[0]; sD[0][roff + 16][c0 + 1] = accA1[1];
                    sD[0][roff + 24][c0] = accA1[2]; sD[0][roff + 24][c0 + 1] = accA1[3];
                    sD[1][roff +  0][c0] = accB0[0]; sD[1][roff +  0][c0 + 1] = accB0[1];
                    sD[1][roff +  8][c0] = accB0[2]; sD[1][roff +  8][c0 + 1] = accB0[3];
                    sD[1][roff + 16][c0] = accB1[0]; sD[1][roff + 16][c0 + 1] = accB1[1];
                    sD[1][roff + 24][c0] = accB1[2]; sD[1][roff + 24][c0 + 1] = accB1[3];
                } else {
                    sD[0][roff +  0][c0] += accA0[0]; sD[0][roff +  0][c0 + 1] += accA0[1];
                    sD[0][roff +  8][c0] += accA0[2]; sD[0][roff +  8][c0 + 1] += accA0[3];
                    sD[0][roff + 16][c0] += accA1[0]; sD[0][roff + 16][c0 + 1] += accA1[1];
                    sD[0][roff + 24][c0] += accA1[2]; sD[0][roff + 24][c0 + 1] += accA1[3];
                    sD[1][roff +  0][c0] += accB0[0]; sD[1][roff +  0][c0 + 1] += accB0[1];
                    sD[1][roff +  8][c0] += accB0[2]; sD[1][roff +  8][c0 + 1] += accB0[3];
                    sD[1][roff + 16][c0] += accB1[0]; sD[1][roff + 16][c0 + 1] += accB1[1];
                    sD[1][roff + 24][c0] += accB1[2]; sD[1][roff + 24][c0 + 1] += accB1[3];
                }
            }
            __syncthreads();
        }
    }

    // ---- epilogue: tail, clip, A2-weight, per-b reduce ----
    {
        int b = t & 31;                // local b column 0..31
        int grp = t >> 5;              // 0..15, each handles 4 of 64 rows
        float local = 0.f;
        #pragma unroll
        for (int rr = 0; rr < 4; rr++) {
            int idx = grp * 4 + rr;    // 0..63
            int tile = idx >> 5;
            int row = idx & 31;
            int i = (tile ? I0B : I0A) + row;
            float ssuf = (i == 0) ? 0.f : sSuf[1024 - i];
            float wb1 = sD[tile][row][b] + (1.f - ba) + SIG10 * ssuf;
            local += sA2f[i] * (1.f - clamp01(wb1));
        }
        sBlk[t] = local;
    }
    __syncthreads();
    if (t < 32) {
        float S = 0.f;
        #pragma unroll
        for (int g = 0; g < 16; g++) S += sBlk[t + 32 * g];
        d_Spart[br][tp][bhalf * 32 + t] = S;
    }

    // ---- last-CTA final combine ----
    __threadfence();
    if (t == 0) {
        int v = atomicAdd(&d_ctr, 1);
        sDone = (v == NGEMM - 1) ? 1 : 0;
    }
    __syncthreads();
    if (sDone) {
        if (t < BATCH) {
            float e0 = __expf(A4[0]), e1 = __expf(A4[1]), e2 = __expf(A4[2]);
            float sinv = __fdividef(1.f, e0 + e1 + e2);
            float a40 = e0 * sinv, a41 = e1 * sinv, a42 = e2 * sinv;
            volatile float* vs = (volatile float*)d_Spart;   // [3][16][64]
            float Sb[3];
            #pragma unroll
            for (int r = 0; r < 3; r++) {
                float acc = 0.f;
                #pragma unroll
                for (int p = 0; p < 16; p++) acc += vs[(r * 16 + p) * 64 + t];
                Sb[r] = acc;
            }
            float r0 = clamp01(bb1[0] - Sb[0]);
            float r1 = clamp01(bb2[0] - Sb[1]);
            float r2 = clamp01(bb3[0] - Sb[2]);
            float acc4 = beta4p[0];
            acc4 -= a40 * (1.f - r0);
            acc4 -= a41 * (1.f - r1);
            acc4 -= a42 * (1.f - r2);
            out[t] = clamp01(acc4);
        }
        if (t == 0) d_ctr = 0;
    }
}

extern "C" void kernel_launch(void* const* d_in, const int* in_sizes, int n_in,
                              void* d_out, int out_size)
{
    const float* x1      = (const float*)d_in[0];
    const float* x2      = (const float*)d_in[1];
    const float* x3      = (const float*)d_in[2];
    const float* t1      = (const float*)d_in[3];
    const float* b1      = (const float*)d_in[4];
    const float* A1_1    = (const float*)d_in[5];
    const float* A2_1    = (const float*)d_in[6];
    const float* beta1_1 = (const float*)d_in[7];
    const float* beta1_2 = (const float*)d_in[8];
    const float* t2      = (const float*)d_in[9];
    const float* b2      = (const float*)d_in[10];
    const float* A1_2    = (const float*)d_in[11];
    const float* A2_2    = (const float*)d_in[12];
    const float* beta2_1 = (const float*)d_in[13];
    const float* beta2_2 = (const float*)d_in[14];
    const float* t3      = (const float*)d_in[15];
    const float* b3      = (const float*)d_in[16];
    const float* A1_3    = (const float*)d_in[17];
    const float* A2_3    = (const float*)d_in[18];
    const float* beta3_1 = (const float*)d_in[19];
    const float* beta3_2 = (const float*)d_in[20];
    const float* A4      = (const float*)d_in[21];
    const float* beta4   = (const float*)d_in[22];
    float* out = (float*)d_out;

    setup_kernel<<<192, 128>>>(x1, x2, x3, t1, b1, t2, b2, t3, b3);
    gemm_kernel<<<NGEMM, 512>>>(A1_1, A1_2, A1_3,
                                A2_1, A2_2, A2_3,
                                beta1_1, beta2_1, beta3_1,
                                beta1_2, beta2_2, beta3_2,
                                A4, beta4, out);
}

// round 11
// speedup vs baseline: 1.4157x; 1.0017x over previous
#include <cuda_runtime.h>
#include <cuda_bf16.h>
#include <cstdint>

#define T 1024
#define BATCH 64
#define NGEMM 96            // 3 branches * 16 tile-pairs * 2 b-halves

// ---------------- device scratch (no allocations allowed) ----------------
// Interleaved bf16 splits of sigmoid rows: word m covers k = 2m, 2m+1;
// d_g[br][b][m] = (hi_word, lo_word).
__device__ uint2 d_g[3][BATCH][T / 2];
__device__ float d_Spart[3][16][BATCH];         // per-branch, per-pair partial S
__device__ int   d_ctr;                         // finisher counter (reset each run)

__device__ __forceinline__ float clamp01(float v) { return fminf(fmaxf(v, 0.f), 1.f); }
__device__ __forceinline__ unsigned short f2bf(float f) {
    return __bfloat16_as_ushort(__float2bfloat16(f));
}
__device__ __forceinline__ float bf2f(unsigned short u) {
    return __bfloat162float(__ushort_as_bfloat16(u));
}

// m16n8k16 bf16 HMMA, fp32 accum in place (baseline ISA, works on sm_103)
__device__ __forceinline__ void hmma(float* d, uint32_t a0, uint32_t a1,
                                     uint32_t a2, uint32_t a3,
                                     uint32_t b0, uint32_t b1) {
    asm volatile(
        "mma.sync.aligned.m16n8k16.row.col.f32.bf16.bf16.f32 "
        "{%0,%1,%2,%3}, {%4,%5,%6,%7}, {%8,%9}, {%0,%1,%2,%3};"
        : "+f"(d[0]), "+f"(d[1]), "+f"(d[2]), "+f"(d[3])
        : "r"(a0), "r"(a1), "r"(a2), "r"(a3), "r"(b0), "r"(b1));
}

// ---------------------------------------------------------------------------
// Setup kernel: sigmoid rows -> interleaved bf16 hi/lo words. 192 blocks x 128.
// ---------------------------------------------------------------------------
__global__ void __launch_bounds__(128) setup_kernel(
    const float* __restrict__ x1, const float* __restrict__ x2, const float* __restrict__ x3,
    const float* __restrict__ t1p, const float* __restrict__ b1p,
    const float* __restrict__ t2p, const float* __restrict__ b2p,
    const float* __restrict__ t3p, const float* __restrict__ b3p)
{
    int bid = blockIdx.x;
    int br = bid >> 6;
    int b = bid & 63;
    const float* xs = (br == 0) ? x1 : (br == 1) ? x2 : x3;
    const float* tp = (br == 0) ? t1p : (br == 1) ? t2p : t3p;
    const float* bp = (br == 0) ? b1p : (br == 1) ? b2p : b3p;
    float tv = tp[0], bv = bp[0];
    int t = threadIdx.x;

    const float* xr = xs + b * T;
    float xv[8];
    *(float4*)(xv + 0) = *(const float4*)(xr + 8 * t);
    *(float4*)(xv + 4) = *(const float4*)(xr + 8 * t + 4);

    uint2 outw[4];
    #pragma unroll
    for (int q = 0; q < 4; q++) {
        unsigned short h2[2], l2[2];
        #pragma unroll
        for (int e = 0; e < 2; e++) {
            float prod = __fmul_rn(xv[2 * q + e], tv);   // no contraction: exact r==b test
            float r = __fsub_rn(bv, prod);
            if (r == bv) r = -10.f;
            float g = __fdividef(1.f, 1.f + __expf(-r));
            h2[e] = f2bf(g);
            l2[e] = f2bf(g - bf2f(h2[e]));
        }
        outw[q].x = (uint32_t)h2[0] | ((uint32_t)h2[1] << 16);
        outw[q].y = (uint32_t)l2[0] | ((uint32_t)l2[1] << 16);
    }
    uint2* dst = &d_g[br][b][4 * t];
    *(uint4*)(dst + 0) = make_uint4(outw[0].x, outw[0].y, outw[1].x, outw[1].y);
    *(uint4*)(dst + 2) = make_uint4(outw[2].x, outw[2].y, outw[3].x, outw[3].y);
}

// ---------------------------------------------------------------------------
// GEMM kernel: 96 CTAs x 512 threads. CTA = (br, pair tp, bhalf).
// Two mirrored 32-row i-tiles; 16 warps = (4 col-groups of 8 b) x (4 k-parities).
// A fragments from zero-padded bf16 a1sm (Toeplitz; a3 == a0).
// B prefetched through a 4-deep register ring (16 k-steps of distance).
// ---------------------------------------------------------------------------
#define AESZ 1112   // u16 entries per ext array (idx = 32 + (k - i), zeros outside)

__global__ void __launch_bounds__(512) gemm_kernel(
    const float* __restrict__ A1a, const float* __restrict__ A1b, const float* __restrict__ A1c,
    const float* __restrict__ A2a, const float* __restrict__ A2b, const float* __restrict__ A2c,
    const float* __restrict__ ba1, const float* __restrict__ ba2, const float* __restrict__ ba3,
    const float* __restrict__ bb1, const float* __restrict__ bb2, const float* __restrict__ bb3,
    const float* __restrict__ A4, const float* __restrict__ beta4p,
    float* __restrict__ out)
{
    __shared__ __align__(16) unsigned short aeh0[AESZ], aeh1[AESZ];
    __shared__ __align__(16) unsigned short ael0[AESZ], ael1[AESZ];
    __shared__ __align__(16) float sAf[1024];
    __shared__ __align__(16) float sSuf[1024];
    __shared__ __align__(16) float sA2f[1024];
    __shared__ __align__(16) float sD[2][32][34];
    __shared__ float sBlk[512];
    __shared__ float sRA[16], sRB[16], sWsum[16], sWexcl[16];
    __shared__ int sDone;

    const float SIG10 = 4.5397868702434395e-05f;

    int bid = blockIdx.x;
    int br = bid >> 5;                 // 0..2
    int rem = bid & 31;
    int tp = rem >> 1;                 // pair 0..15
    int bhalf = rem & 1;
    int I0A = 32 * tp;
    int I0B = 32 * (31 - tp);
    int nk  = 64 - 2 * tp;             // k-steps from I0A to 1024
    int ksB = 2 * (31 - 2 * tp);       // first k-step overlapping tile B

    const float* A1  = (br == 0) ? A1a : (br == 1) ? A1b : A1c;
    const float* A2  = (br == 0) ? A2a : (br == 1) ? A2b : A2c;
    const float* bap = (br == 0) ? ba1 : (br == 1) ? ba2 : ba3;

    int t = threadIdx.x;
    int w = t >> 5, l = t & 31;
    int roff = l >> 2;                 // fragment row offset 0..7
    int cq = l & 3;                    // fragment k-pair 0..3
    int colg = w & 3;                  // col group (8 b each)
    int kpar = w >> 2;                 // k parity 0..3

    // ---- preamble: fp32 softmax(A1)+suffix scan, softmax(A2) (512 thr) ----
    float ba = bap[0];
    {
        float2 v1 = *(const float2*)(A1 + 2 * t);
        float2 v2 = *(const float2*)(A2 + 2 * t);
        float m1 = fmaxf(v1.x, v1.y);
        float m2 = fmaxf(v2.x, v2.y);
        #pragma unroll
        for (int off = 16; off; off >>= 1) {
            m1 = fmaxf(m1, __shfl_xor_sync(0xffffffffu, m1, off));
            m2 = fmaxf(m2, __shfl_xor_sync(0xffffffffu, m2, off));
        }
        if (l == 0) { sRA[w] = m1; sRB[w] = m2; }
        __syncthreads();
        if (t == 0) {
            float a = sRA[0], b2 = sRB[0];
            #pragma unroll
            for (int k = 1; k < 16; k++) { a = fmaxf(a, sRA[k]); b2 = fmaxf(b2, sRB[k]); }
            sRA[0] = a; sRB[0] = b2;
        }
        __syncthreads();
        m1 = sRA[0]; m2 = sRB[0];
        __syncthreads();

        float e10 = __expf(v1.x - m1), e11 = __expf(v1.y - m1);
        float e20 = __expf(v2.x - m2), e21 = __expf(v2.y - m2);
        float s1 = e10 + e11, s2 = e20 + e21;
        #pragma unroll
        for (int off = 16; off; off >>= 1) {
            s1 += __shfl_xor_sync(0xffffffffu, s1, off);
            s2 += __shfl_xor_sync(0xffffffffu, s2, off);
        }
        if (l == 0) { sRA[w] = s1; sRB[w] = s2; }
        __syncthreads();
        if (t == 0) {
            float a = sRA[0], b2 = sRB[0];
            #pragma unroll
            for (int k = 1; k < 16; k++) { a += sRA[k]; b2 += sRB[k]; }
            sRA[0] = a; sRB[0] = b2;
        }
        __syncthreads();
        s1 = sRA[0]; s2 = sRB[0];
        __syncthreads();

        float inv1 = __fdividef(1.f, s1), inv2 = __fdividef(1.f, s2);
        float a0 = e10 * inv1, a1v = e11 * inv1;
        *(float2*)(sAf + 2 * t) = make_float2(a0, a1v);
        *(float2*)(sA2f + 2 * t) = make_float2(e20 * inv2, e21 * inv2);

        // inclusive suffix scan over 2-element thread chunks
        float sn = a0 + a1v;
        float s = sn;
        #pragma unroll
        for (int off = 1; off < 32; off <<= 1) {
            float o = __shfl_down_sync(0xffffffffu, s, off);
            if (l + off < 32) s += o;
        }
        if (l == 0) sWsum[w] = s;
        __syncthreads();
        if (t < 16) {
            float tot = 0.f;
            for (int k = t + 1; k < 16; k++) tot += sWsum[k];
            sWexcl[t] = tot;
        }
        __syncthreads();
        float after = (s - sn) + sWexcl[w];   // strictly-after my chunk
        float v1s = after + a1v;
        float v0s = v1s + a0;
        sSuf[2 * t + 1] = v1s;
        sSuf[2 * t + 0] = v0s;
    }
    __syncthreads();

    // ---- build zero-padded bf16 split arrays (+1-shifted copies) ----
    for (int x = t; x < AESZ; x += 512) {
        float v0 = (x >= 32 && x < 1056) ? sAf[x - 32] : 0.f;
        float v1 = (x + 1 >= 32 && x + 1 < 1056) ? sAf[x - 31] : 0.f;
        unsigned short h0 = f2bf(v0);
        unsigned short h1 = f2bf(v1);
        aeh0[x] = h0; ael0[x] = f2bf(v0 - bf2f(h0));
        aeh1[x] = h1; ael1[x] = f2bf(v1 - bf2f(h1));
    }
    __syncthreads();

    // ---- main K loop (warp handles ks = kpar, kpar+4, ...) ----
    const uint32_t* Ah = (const uint32_t*)((roff & 1) ? aeh1 : aeh0);
    const uint32_t* Al = (const uint32_t*)((roff & 1) ? ael1 : ael0);
    int Pc = 32 + 2 * cq - roff;       // thread-constant base (u16 units)

    int n = bhalf * 32 + 8 * colg + roff;
    const uint2* gn = &d_g[br][n][0];

    float accA0[4] = {0, 0, 0, 0}, accA1[4] = {0, 0, 0, 0};
    float accB0[4] = {0, 0, 0, 0}, accB1[4] = {0, 0, 0, 0};

    // 4-deep B prefetch ring: slot r holds (B_lo16, B_hi16) uint2 pair for
    // k-step ks = kpar + 4*(it_base + r). Distance = 16 k-steps.
    uint2 bq[4][2];
    #pragma unroll
    for (int r = 0; r < 4; r++) {
        int ksr = kpar + 4 * r;
        if (ksr >= nk) ksr = kpar;
        int kw = ((I0A + 16 * ksr) >> 1) + cq;
        bq[r][0] = __ldg(gn + kw);
        bq[r][1] = __ldg(gn + kw + 4);
    }

    int it = 0;
    for (int ks = kpar; ks < nk; ks += 4, it++) {
        uint32_t bh0 = bq[it & 3][0].x, bl0 = bq[it & 3][0].y;
        uint32_t bh1 = bq[it & 3][1].x, bl1 = bq[it & 3][1].y;
        if (ks + 16 < nk) {
            int kw = ((I0A + 16 * (ks + 16)) >> 1) + cq;
            bq[it & 3][0] = __ldg(gn + kw);
            bq[it & 3][1] = __ldg(gn + kw + 4);
        }

        // tile A
        {
            int Q0 = (Pc + 16 * ks) >> 1;
            uint32_t uh0 = Ah[Q0 - 12], uh1 = Ah[Q0 - 8], uh2 = Ah[Q0 - 4];
            uint32_t uh3 = Ah[Q0],      uh4 = Ah[Q0 + 4];
            uint32_t ul0 = Al[Q0 - 12], ul1 = Al[Q0 - 8], ul2 = Al[Q0 - 4];
            uint32_t ul3 = Al[Q0],      ul4 = Al[Q0 + 4];
            hmma(accA0, uh3, uh2, uh4, uh3, bh0, bh1);
            hmma(accA0, uh3, uh2, uh4, uh3, bl0, bl1);
            hmma(accA0, ul3, ul2, ul4, ul3, bh0, bh1);
            hmma(accA1, uh1, uh0, uh2, uh1, bh0, bh1);
            hmma(accA1, uh1, uh0, uh2, uh1, bl0, bl1);
            hmma(accA1, ul1, ul0, ul2, ul1, bh0, bh1);
        }
        // tile B (overlap region)
        if (ks >= ksB) {
            int Q0 = (Pc + 16 * (ks - ksB)) >> 1;
            uint32_t uh0 = Ah[Q0 - 12], uh1 = Ah[Q0 - 8], uh2 = Ah[Q0 - 4];
            uint32_t uh3 = Ah[Q0],      uh4 = Ah[Q0 + 4];
            uint32_t ul0 = Al[Q0 - 12], ul1 = Al[Q0 - 8], ul2 = Al[Q0 - 4];
            uint32_t ul3 = Al[Q0],      ul4 = Al[Q0 + 4];
            hmma(accB0, uh3, uh2, uh4, uh3, bh0, bh1);
            hmma(accB0, uh3, uh2, uh4, uh3, bl0, bl1);
            hmma(accB0, ul3, ul2, ul4, ul3, bh0, bh1);
            hmma(accB1, uh1, uh0, uh2, uh1, bh0, bh1);
            hmma(accB1, uh1, uh0, uh2, uh1, bl0, bl1);
            hmma(accB1, ul1, ul0, ul2, ul1, bh0, bh1);
        }
    }

    // ---- merge k-parity partials into sD (4 phased passes) ----
    {
        int c0 = 8 * colg + 2 * cq;
        #pragma unroll
        for (int p = 0; p < 4; p++) {
            if (kpar == p) {
                if (p == 0) {
                    sD[0][roff +  0][c0] = accA0[0]; sD[0][roff +  0][c0 + 1] = accA0[1];
                    sD[0][roff +  8][c0] = accA0[2]; sD[0][roff +  8][c0 + 1] = accA0[3];
                    sD[0][roff + 16][c0] = accA1[0]; sD[0][roff + 16][c0 + 1] = accA1[1];
                    sD[0][roff + 24][c0] = accA1[2]; sD[0][roff + 24][c0 + 1] = accA1[3];
                    sD[1][roff +  0][c0] = accB0[0]; sD[1][roff +  0][c0 + 1] = accB0[1];
                    sD[1][roff +  8][c0] = accB0[2]; sD[1][roff +  8][c0 + 1] = accB0[3];
                    sD[1][roff + 16][c0] = accB1[0]; sD[1][roff + 16][c0 + 1] = accB1[1];
                    sD[1][roff + 24][c0] = accB1[2]; sD[1][roff + 24][c0 + 1] = accB1[3];
                } else {
                    sD[0][roff +  0][c0] += accA0[0]; sD[0][roff +  0][c0 + 1] += accA0[1];
                    sD[0][roff +  8][c0] += accA0[2]; sD[0][roff +  8][c0 + 1] += accA0[3];
                    sD[0][roff + 16][c0] += accA1[0]; sD[0][roff + 16][c0 + 1] += accA1[1];
                    sD[0][roff + 24][c0] += accA1[2]; sD[0][roff + 24][c0 + 1] += accA1[3];
                    sD[1][roff +  0][c0] += accB0[0]; sD[1][roff +  0][c0 + 1] += accB0[1];
                    sD[1][roff +  8][c0] += accB0[2]; sD[1][roff +  8][c0 + 1] += accB0[3];
                    sD[1][roff + 16][c0] += accB1[0]; sD[1][roff + 16][c0 + 1] += accB1[1];
                    sD[1][roff + 24][c0] += accB1[2]; sD[1][roff + 24][c0 + 1] += accB1[3];
                }
            }
            __syncthreads();
        }
    }

    // ---- epilogue: tail, clip, A2-weight, per-b reduce ----
    {
        int b = t & 31;                // local b column 0..31
        int grp = t >> 5;              // 0..15, each handles 4 of 64 rows
        float local = 0.f;
        #pragma unroll
        for (int rr = 0; rr < 4; rr++) {
            int idx = grp * 4 + rr;    // 0..63
            int tile = idx >> 5;
            int row = idx & 31;
            int i = (tile ? I0B : I0A) + row;
            float ssuf = (i == 0) ? 0.f : sSuf[1024 - i];
            float wb1 = sD[tile][row][b] + (1.f - ba) + SIG10 * ssuf;
            local += sA2f[i] * (1.f - clamp01(wb1));
        }
        sBlk[t] = local;
    }
    __syncthreads();
    if (t < 32) {
        float S = 0.f;
        #pragma unroll
        for (int g = 0; g < 16; g++) S += sBlk[t + 32 * g];
        d_Spart[br][tp][bhalf * 32 + t] = S;
    }

    // ---- last-CTA final combine ----
    __threadfence();
    if (t == 0) {
        int v = atomicAdd(&d_ctr, 1);
        sDone = (v == NGEMM - 1) ? 1 : 0;
    }
    __syncthreads();
    if (sDone) {
        if (t < BATCH) {
            float e0 = __expf(A4[0]), e1 = __expf(A4[1]), e2 = __expf(A4[2]);
            float sinv = __fdividef(1.f, e0 + e1 + e2);
            float a40 = e0 * sinv, a41 = e1 * sinv, a42 = e2 * sinv;
            volatile float* vs = (volatile float*)d_Spart;   // [3][16][64]
            float Sb[3];
            #pragma unroll
            for (int r = 0; r < 3; r++) {
                float acc = 0.f;
                #pragma unroll
                for (int p = 0; p < 16; p++) acc += vs[(r * 16 + p) * 64 + t];
                Sb[r] = acc;
            }
            float r0 = clamp01(bb1[0] - Sb[0]);
            float r1 = clamp01(bb2[0] - Sb[1]);
            float r2 = clamp01(bb3[0] - Sb[2]);
            float acc4 = beta4p[0];
            acc4 -= a40 * (1.f - r0);
            acc4 -= a41 * (1.f - r1);
            acc4 -= a42 * (1.f - r2);
            out[t] = clamp01(acc4);
        }
        if (t == 0) d_ctr = 0;
    }
}

extern "C" void kernel_launch(void* const* d_in, const int* in_sizes, int n_in,
                              void* d_out, int out_size)
{
    const float* x1      = (const float*)d_in[0];
    const float* x2      = (const float*)d_in[1];
    const float* x3      = (const float*)d_in[2];
    const float* t1      = (const float*)d_in[3];
    const float* b1      = (const float*)d_in[4];
    const float* A1_1    = (const float*)d_in[5];
    const float* A2_1    = (const float*)d_in[6];
    const float* beta1_1 = (const float*)d_in[7];
    const float* beta1_2 = (const float*)d_in[8];
    const float* t2      = (const float*)d_in[9];
    const float* b2      = (const float*)d_in[10];
    const float* A1_2    = (const float*)d_in[11];
    const float* A2_2    = (const float*)d_in[12];
    const float* beta2_1 = (const float*)d_in[13];
    const float* beta2_2 = (const float*)d_in[14];
    const float* t3      = (const float*)d_in[15];
    const float* b3      = (const float*)d_in[16];
    const float* A1_3    = (const float*)d_in[17];
    const float* A2_3    = (const float*)d_in[18];
    const float* beta3_1 = (const float*)d_in[19];
    const float* beta3_2 = (const float*)d_in[20];
    const float* A4      = (const float*)d_in[21];
    const float* beta4   = (const float*)d_in[22];
    float* out = (float*)d_out;

    setup_kernel<<<192, 128>>>(x1, x2, x3, t1, b1, t2, b2, t3, b3);
    gemm_kernel<<<NGEMM, 512>>>(A1_1, A1_2, A1_3,
                                A2_1, A2_2, A2_3,
                                beta1_1, beta2_1, beta3_1,
                                beta1_2, beta2_2, beta3_2,
                                A4, beta4, out);
}

// round 12
// speedup vs baseline: 1.6061x; 1.1345x over previous
#include <cuda_runtime.h>
#include <cuda_bf16.h>
#include <cstdint>

#define T 1024
#define BATCH 64
#define NGEMM 192           // 3 branches * 16 tile-pairs * 4 b-quarters

// ---------------- device scratch (no allocations allowed) ----------------
// Interleaved bf16 splits of sigmoid rows: word m covers k = 2m, 2m+1;
// d_g[br][b][m] = (hi_word, lo_word).
__device__ uint2 d_g[3][BATCH][T / 2];
__device__ float d_Spart[3][16][BATCH];         // per-branch, per-pair partial S
__device__ int   d_ctr;                         // finisher counter (reset each run)

__device__ __forceinline__ float clamp01(float v) { return fminf(fmaxf(v, 0.f), 1.f); }
__device__ __forceinline__ unsigned short f2bf(float f) {
    return __bfloat16_as_ushort(__float2bfloat16(f));
}
__device__ __forceinline__ float bf2f(unsigned short u) {
    return __bfloat162float(__ushort_as_bfloat16(u));
}

// m16n8k16 bf16 HMMA, fp32 accum in place (baseline ISA, works on sm_103)
__device__ __forceinline__ void hmma(float* d, uint32_t a0, uint32_t a1,
                                     uint32_t a2, uint32_t a3,
                                     uint32_t b0, uint32_t b1) {
    asm volatile(
        "mma.sync.aligned.m16n8k16.row.col.f32.bf16.bf16.f32 "
        "{%0,%1,%2,%3}, {%4,%5,%6,%7}, {%8,%9}, {%0,%1,%2,%3};"
        : "+f"(d[0]), "+f"(d[1]), "+f"(d[2]), "+f"(d[3])
        : "r"(a0), "r"(a1), "r"(a2), "r"(a3), "r"(b0), "r"(b1));
}

// ---------------------------------------------------------------------------
// Setup kernel: sigmoid rows -> interleaved bf16 hi/lo words. 192 blocks x 128.
// ---------------------------------------------------------------------------
__global__ void __launch_bounds__(128) setup_kernel(
    const float* __restrict__ x1, const float* __restrict__ x2, const float* __restrict__ x3,
    const float* __restrict__ t1p, const float* __restrict__ b1p,
    const float* __restrict__ t2p, const float* __restrict__ b2p,
    const float* __restrict__ t3p, const float* __restrict__ b3p)
{
    int bid = blockIdx.x;
    int br = bid >> 6;
    int b = bid & 63;
    const float* xs = (br == 0) ? x1 : (br == 1) ? x2 : x3;
    const float* tp = (br == 0) ? t1p : (br == 1) ? t2p : t3p;
    const float* bp = (br == 0) ? b1p : (br == 1) ? b2p : b3p;
    float tv = tp[0], bv = bp[0];
    int t = threadIdx.x;

    const float* xr = xs + b * T;
    float xv[8];
    *(float4*)(xv + 0) = *(const float4*)(xr + 8 * t);
    *(float4*)(xv + 4) = *(const float4*)(xr + 8 * t + 4);

    uint2 outw[4];
    #pragma unroll
    for (int q = 0; q < 4; q++) {
        unsigned short h2[2], l2[2];
        #pragma unroll
        for (int e = 0; e < 2; e++) {
            float prod = __fmul_rn(xv[2 * q + e], tv);   // no contraction: exact r==b test
            float r = __fsub_rn(bv, prod);
            if (r == bv) r = -10.f;
            float g = __fdividef(1.f, 1.f + __expf(-r));
            h2[e] = f2bf(g);
            l2[e] = f2bf(g - bf2f(h2[e]));
        }
        outw[q].x = (uint32_t)h2[0] | ((uint32_t)h2[1] << 16);
        outw[q].y = (uint32_t)l2[0] | ((uint32_t)l2[1] << 16);
    }
    uint2* dst = &d_g[br][b][4 * t];
    *(uint4*)(dst + 0) = make_uint4(outw[0].x, outw[0].y, outw[1].x, outw[1].y);
    *(uint4*)(dst + 2) = make_uint4(outw[2].x, outw[2].y, outw[3].x, outw[3].y);
}

// ---------------------------------------------------------------------------
// GEMM kernel: 192 CTAs x 512 threads, 2 CTAs/SM. CTA = (br, pair tp, bq).
// Two mirrored 32-row i-tiles; 16 b-columns per CTA.
// 16 warps = (2 col-groups of 8 b) x (8 k-parities).
// A fragments from zero-padded bf16 a1sm (Toeplitz; a3 == a0).
// ---------------------------------------------------------------------------
#define AESZ 1112   // u16 entries per ext array (idx = 32 + (k - i), zeros outside)

__global__ void __launch_bounds__(512, 2) gemm_kernel(
    const float* __restrict__ A1a, const float* __restrict__ A1b, const float* __restrict__ A1c,
    const float* __restrict__ A2a, const float* __restrict__ A2b, const float* __restrict__ A2c,
    const float* __restrict__ ba1, const float* __restrict__ ba2, const float* __restrict__ ba3,
    const float* __restrict__ bb1, const float* __restrict__ bb2, const float* __restrict__ bb3,
    const float* __restrict__ A4, const float* __restrict__ beta4p,
    float* __restrict__ out)
{
    __shared__ __align__(16) unsigned short aeh0[AESZ], aeh1[AESZ];
    __shared__ __align__(16) unsigned short ael0[AESZ], ael1[AESZ];
    __shared__ __align__(16) float sAf[1024];
    __shared__ __align__(16) float sSuf[1024];
    __shared__ __align__(16) float sA2f[1024];
    __shared__ __align__(16) float sD[2][32][18];
    __shared__ float sBlk[512];
    __shared__ float sRA[16], sRB[16], sWsum[16], sWexcl[16];
    __shared__ int sDone;

    const float SIG10 = 4.5397868702434395e-05f;

    int bid = blockIdx.x;
    int br = bid >> 6;                 // 0..2
    int rem = bid & 63;
    int tp = rem >> 2;                 // pair 0..15
    int bq = rem & 3;                  // b-quarter (16 cols)
    int I0A = 32 * tp;
    int I0B = 32 * (31 - tp);
    int nk  = 64 - 2 * tp;             // k-steps from I0A to 1024
    int ksB = 2 * (31 - 2 * tp);       // first k-step overlapping tile B

    const float* A1  = (br == 0) ? A1a : (br == 1) ? A1b : A1c;
    const float* A2  = (br == 0) ? A2a : (br == 1) ? A2b : A2c;
    const float* bap = (br == 0) ? ba1 : (br == 1) ? ba2 : ba3;

    int t = threadIdx.x;
    int w = t >> 5, l = t & 31;
    int roff = l >> 2;                 // fragment row offset 0..7
    int cq = l & 3;                    // fragment k-pair 0..3
    int colg = w & 1;                  // col group (8 b each)
    int kpar = w >> 1;                 // k parity 0..7

    // ---- preamble: fp32 softmax(A1)+suffix scan, softmax(A2) (512 thr) ----
    float ba = bap[0];
    {
        float2 v1 = *(const float2*)(A1 + 2 * t);
        float2 v2 = *(const float2*)(A2 + 2 * t);
        float m1 = fmaxf(v1.x, v1.y);
        float m2 = fmaxf(v2.x, v2.y);
        #pragma unroll
        for (int off = 16; off; off >>= 1) {
            m1 = fmaxf(m1, __shfl_xor_sync(0xffffffffu, m1, off));
            m2 = fmaxf(m2, __shfl_xor_sync(0xffffffffu, m2, off));
        }
        if (l == 0) { sRA[w] = m1; sRB[w] = m2; }
        __syncthreads();
        if (t == 0) {
            float a = sRA[0], b2 = sRB[0];
            #pragma unroll
            for (int k = 1; k < 16; k++) { a = fmaxf(a, sRA[k]); b2 = fmaxf(b2, sRB[k]); }
            sRA[0] = a; sRB[0] = b2;
        }
        __syncthreads();
        m1 = sRA[0]; m2 = sRB[0];
        __syncthreads();

        float e10 = __expf(v1.x - m1), e11 = __expf(v1.y - m1);
        float e20 = __expf(v2.x - m2), e21 = __expf(v2.y - m2);
        float s1 = e10 + e11, s2 = e20 + e21;
        #pragma unroll
        for (int off = 16; off; off >>= 1) {
            s1 += __shfl_xor_sync(0xffffffffu, s1, off);
            s2 += __shfl_xor_sync(0xffffffffu, s2, off);
        }
        if (l == 0) { sRA[w] = s1; sRB[w] = s2; }
        __syncthreads();
        if (t == 0) {
            float a = sRA[0], b2 = sRB[0];
            #pragma unroll
            for (int k = 1; k < 16; k++) { a += sRA[k]; b2 += sRB[k]; }
            sRA[0] = a; sRB[0] = b2;
        }
        __syncthreads();
        s1 = sRA[0]; s2 = sRB[0];
        __syncthreads();

        float inv1 = __fdividef(1.f, s1), inv2 = __fdividef(1.f, s2);
        float a0 = e10 * inv1, a1v = e11 * inv1;
        *(float2*)(sAf + 2 * t) = make_float2(a0, a1v);
        *(float2*)(sA2f + 2 * t) = make_float2(e20 * inv2, e21 * inv2);

        // inclusive suffix scan over 2-element thread chunks
        float sn = a0 + a1v;
        float s = sn;
        #pragma unroll
        for (int off = 1; off < 32; off <<= 1) {
            float o = __shfl_down_sync(0xffffffffu, s, off);
            if (l + off < 32) s += o;
        }
        if (l == 0) sWsum[w] = s;
        __syncthreads();
        if (t < 16) {
            float tot = 0.f;
            for (int k = t + 1; k < 16; k++) tot += sWsum[k];
            sWexcl[t] = tot;
        }
        __syncthreads();
        float after = (s - sn) + sWexcl[w];   // strictly-after my chunk
        float v1s = after + a1v;
        float v0s = v1s + a0;
        sSuf[2 * t + 1] = v1s;
        sSuf[2 * t + 0] = v0s;
    }
    __syncthreads();

    // ---- build zero-padded bf16 split arrays (+1-shifted copies) ----
    for (int x = t; x < AESZ; x += 512) {
        float v0 = (x >= 32 && x < 1056) ? sAf[x - 32] : 0.f;
        float v1 = (x + 1 >= 32 && x + 1 < 1056) ? sAf[x - 31] : 0.f;
        unsigned short h0 = f2bf(v0);
        unsigned short h1 = f2bf(v1);
        aeh0[x] = h0; ael0[x] = f2bf(v0 - bf2f(h0));
        aeh1[x] = h1; ael1[x] = f2bf(v1 - bf2f(h1));
    }
    __syncthreads();

    // ---- main K loop (warp handles ks = kpar, kpar+8, ...) ----
    const uint32_t* Ah = (const uint32_t*)((roff & 1) ? aeh1 : aeh0);
    const uint32_t* Al = (const uint32_t*)((roff & 1) ? ael1 : ael0);
    int Pc = 32 + 2 * cq - roff;       // thread-constant base (u16 units)

    int n = bq * 16 + 8 * colg + roff;
    const uint2* gn = &d_g[br][n][0];

    float accA0[4] = {0, 0, 0, 0}, accA1[4] = {0, 0, 0, 0};
    float accB0[4] = {0, 0, 0, 0}, accB1[4] = {0, 0, 0, 0};

    // 2-deep B prefetch ring (stride 8 k-steps -> 16 k-steps of distance)
    uint2 bqr[2][2];
    {
        int k0 = kpar;
        int k1 = (kpar + 8 < nk) ? (kpar + 8) : kpar;
        int kw0 = ((I0A + 16 * k0) >> 1) + cq;
        int kw1 = ((I0A + 16 * k1) >> 1) + cq;
        bqr[0][0] = __ldg(gn + kw0); bqr[0][1] = __ldg(gn + kw0 + 4);
        bqr[1][0] = __ldg(gn + kw1); bqr[1][1] = __ldg(gn + kw1 + 4);
    }

    int it = 0;
    for (int ks = kpar; ks < nk; ks += 8, it++) {
        uint32_t bh0 = bqr[it & 1][0].x, bl0 = bqr[it & 1][0].y;
        uint32_t bh1 = bqr[it & 1][1].x, bl1 = bqr[it & 1][1].y;
        if (ks + 16 < nk) {
            int kw = ((I0A + 16 * (ks + 16)) >> 1) + cq;
            bqr[it & 1][0] = __ldg(gn + kw);
            bqr[it & 1][1] = __ldg(gn + kw + 4);
        }

        // tile A
        {
            int Q0 = (Pc + 16 * ks) >> 1;
            uint32_t uh0 = Ah[Q0 - 12], uh1 = Ah[Q0 - 8], uh2 = Ah[Q0 - 4];
            uint32_t uh3 = Ah[Q0],      uh4 = Ah[Q0 + 4];
            uint32_t ul0 = Al[Q0 - 12], ul1 = Al[Q0 - 8], ul2 = Al[Q0 - 4];
            uint32_t ul3 = Al[Q0],      ul4 = Al[Q0 + 4];
            hmma(accA0, uh3, uh2, uh4, uh3, bh0, bh1);
            hmma(accA0, uh3, uh2, uh4, uh3, bl0, bl1);
            hmma(accA0, ul3, ul2, ul4, ul3, bh0, bh1);
            hmma(accA1, uh1, uh0, uh2, uh1, bh0, bh1);
            hmma(accA1, uh1, uh0, uh2, uh1, bl0, bl1);
            hmma(accA1, ul1, ul0, ul2, ul1, bh0, bh1);
        }
        // tile B (overlap region)
        if (ks >= ksB) {
            int Q0 = (Pc + 16 * (ks - ksB)) >> 1;
            uint32_t uh0 = Ah[Q0 - 12], uh1 = Ah[Q0 - 8], uh2 = Ah[Q0 - 4];
            uint32_t uh3 = Ah[Q0],      uh4 = Ah[Q0 + 4];
            uint32_t ul0 = Al[Q0 - 12], ul1 = Al[Q0 - 8], ul2 = Al[Q0 - 4];
            uint32_t ul3 = Al[Q0],      ul4 = Al[Q0 + 4];
            hmma(accB0, uh3, uh2, uh4, uh3, bh0, bh1);
            hmma(accB0, uh3, uh2, uh4, uh3, bl0, bl1);
            hmma(accB0, ul3, ul2, ul4, ul3, bh0, bh1);
            hmma(accB1, uh1, uh0, uh2, uh1, bh0, bh1);
            hmma(accB1, uh1, uh0, uh2, uh1, bl0, bl1);
            hmma(accB1, ul1, ul0, ul2, ul1, bh0, bh1);
        }
    }

    // ---- merge k-parity partials into sD (8 phased passes) ----
    {
        int c0 = 8 * colg + 2 * cq;
        #pragma unroll
        for (int p = 0; p < 8; p++) {
            if (kpar == p) {
                if (p == 0) {
                    sD[0][roff +  0][c0] = accA0[0]; sD[0][roff +  0][c0 + 1] = accA0[1];
                    sD[0][roff +  8][c0] = accA0[2]; sD[0][roff +  8][c0 + 1] = accA0[3];
                    sD[0][roff + 16][c0] = accA1[0]; sD[0][roff + 16][c0 + 1] = accA1[1];
                    sD[0][roff + 24][c0] = accA1[2]; sD[0][roff + 24][c0 + 1] = accA1[3];
                    sD[1][roff +  0][c0] = accB0[0]; sD[1][roff +  0][c0 + 1] = accB0[1];
                    sD[1][roff +  8][c0] = accB0[2]; sD[1][roff +  8][c0 + 1] = accB0[3];
                    sD[1][roff + 16][c0] = accB1[0]; sD[1][roff + 16][c0 + 1] = accB1[1];
                    sD[1][roff + 24][c0] = accB1[2]; sD[1][roff + 24][c0 + 1] = accB1[3];
                } else {
                    sD[0][roff +  0][c0] += accA0[0]; sD[0][roff +  0][c0 + 1] += accA0[1];
                    sD[0][roff +  8][c0] += accA0[2]; sD[0][roff +  8][c0 + 1] += accA0[3];
                    sD[0][roff + 16][c0] += accA1[0]; sD[0][roff + 16][c0 + 1] += accA1[1];
                    sD[0][roff + 24][c0] += accA1[2]; sD[0][roff + 24][c0 + 1] += accA1[3];
                    sD[1][roff +  0][c0] += accB0[0]; sD[1][roff +  0][c0 + 1] += accB0[1];
                    sD[1][roff +  8][c0] += accB0[2]; sD[1][roff +  8][c0 + 1] += accB0[3];
                    sD[1][roff + 16][c0] += accB1[0]; sD[1][roff + 16][c0 + 1] += accB1[1];
                    sD[1][roff + 24][c0] += accB1[2]; sD[1][roff + 24][c0 + 1] += accB1[3];
                }
            }
            __syncthreads();
        }
    }

    // ---- epilogue: tail, clip, A2-weight, per-b reduce ----
    {
        int b = t & 15;                // local b column 0..15
        int grp = t >> 4;              // 0..31, each handles 2 of 64 rows
        float local = 0.f;
        #pragma unroll
        for (int rr = 0; rr < 2; rr++) {
            int idx = grp * 2 + rr;    // 0..63
            int tile = idx >> 5;
            int row = idx & 31;
            int i = (tile ? I0B : I0A) + row;
            float ssuf = (i == 0) ? 0.f : sSuf[1024 - i];
            float wb1 = sD[tile][row][b] + (1.f - ba) + SIG10 * ssuf;
            local += sA2f[i] * (1.f - clamp01(wb1));
        }
        sBlk[t] = local;
    }
    __syncthreads();
    if (t < 16) {
        float S = 0.f;
        #pragma unroll
        for (int g = 0; g < 32; g++) S += sBlk[t + 16 * g];
        d_Spart[br][tp][bq * 16 + t] = S;
    }

    // ---- last-CTA final combine ----
    __threadfence();
    if (t == 0) {
        int v = atomicAdd(&d_ctr, 1);
        sDone = (v == NGEMM - 1) ? 1 : 0;
    }
    __syncthreads();
    if (sDone) {
        if (t < BATCH) {
            float e0 = __expf(A4[0]), e1 = __expf(A4[1]), e2 = __expf(A4[2]);
            float sinv = __fdividef(1.f, e0 + e1 + e2);
            float a40 = e0 * sinv, a41 = e1 * sinv, a42 = e2 * sinv;
            volatile float* vs = (volatile float*)d_Spart;   // [3][16][64]
            float Sb[3];
            #pragma unroll
            for (int r = 0; r < 3; r++) {
                float acc = 0.f;
                #pragma unroll
                for (int p = 0; p < 16; p++) acc += vs[(r * 16 + p) * 64 + t];
                Sb[r] = acc;
            }
            float r0 = clamp01(bb1[0] - Sb[0]);
            float r1 = clamp01(bb2[0] - Sb[1]);
            float r2 = clamp01(bb3[0] - Sb[2]);
            float acc4 = beta4p[0];
            acc4 -= a40 * (1.f - r0);
            acc4 -= a41 * (1.f - r1);
            acc4 -= a42 * (1.f - r2);
            out[t] = clamp01(acc4);
        }
        if (t == 0) d_ctr = 0;
    }
}

extern "C" void kernel_launch(void* const* d_in, const int* in_sizes, int n_in,
                              void* d_out, int out_size)
{
    const float* x1      = (const float*)d_in[0];
    const float* x2      = (const float*)d_in[1];
    const float* x3      = (const float*)d_in[2];
    const float* t1      = (const float*)d_in[3];
    const float* b1      = (const float*)d_in[4];
    const float* A1_1    = (const float*)d_in[5];
    const float* A2_1    = (const float*)d_in[6];
    const float* beta1_1 = (const float*)d_in[7];
    const float* beta1_2 = (const float*)d_in[8];
    const float* t2      = (const float*)d_in[9];
    const float* b2      = (const float*)d_in[10];
    const float* A1_2    = (const float*)d_in[11];
    const float* A2_2    = (const float*)d_in[12];
    const float* beta2_1 = (const float*)d_in[13];
    const float* beta2_2 = (const float*)d_in[14];
    const float* t3      = (const float*)d_in[15];
    const float* b3      = (const float*)d_in[16];
    const float* A1_3    = (const float*)d_in[17];
    const float* A2_3    = (const float*)d_in[18];
    const float* beta3_1 = (const float*)d_in[19];
    const float* beta3_2 = (const float*)d_in[20];
    const float* A4      = (const float*)d_in[21];
    const float* beta4   = (const float*)d_in[22];
    float* out = (float*)d_out;

    setup_kernel<<<192, 128>>>(x1, x2, x3, t1, b1, t2, b2, t3, b3);
    gemm_kernel<<<NGEMM, 512>>>(A1_1, A1_2, A1_3,
                                A2_1, A2_2, A2_3,
                                beta1_1, beta2_1, beta3_1,
                                beta1_2, beta2_2, beta3_2,
                                A4, beta4, out);
}